// round 1
// baseline (speedup 1.0000x reference)
#include <cuda_runtime.h>
#include <cstdint>

#define NCH 128      // input channels i
#define HW  14       // spatial h, w
#define NJ  32       // output channels j
#define SLICES 4     // (n,h) slices per block
#define THREADS 128

#define XS_STRIDE 16                              // floats per (slice,i) row: [0]=0, [1..14]=rolled x, [15]=0
#define XS_SIZE  (SLICES * NCH * XS_STRIDE)       // 8192 floats = 32 KB
#define WS_SIZE  (3 * NCH * NJ)                   // 12288 floats = 48 KB, layout [k][i][j]
#define SMEM_BYTES ((XS_SIZE + WS_SIZE) * 4)      // 81920 B -> 2 CTAs/SM

__device__ __forceinline__ unsigned long long pack2(float v) {
    unsigned long long r;
    asm("mov.b64 %0, {%1, %1};" : "=l"(r) : "f"(v));
    return r;
}

__device__ __forceinline__ void fma2(unsigned long long& d,
                                     unsigned long long a,
                                     unsigned long long b) {
    // packed fp32x2 FMA (Blackwell): d = a*b + d, per 32-bit lane
    asm("fma.rn.f32x2 %0, %1, %2, %0;" : "+l"(d) : "l"(a), "l"(b));
}

// OFS: offset of position w0 within the loaded 12-float window (0 for wg=0, 3 for wg=1)
template <int OFS>
__device__ __forceinline__ void run_i_loop(const float* xrow,
                                           const unsigned long long* wp,
                                           unsigned long long (&acc)[7]) {
#pragma unroll 2
    for (int i = 0; i < NCH; ++i) {
        // x row for this (slice, i): 12 floats covering positions base..base+11
        float4 a = *(const float4*)(xrow + 0);
        float4 b = *(const float4*)(xrow + 4);
        float4 c = *(const float4*)(xrow + 8);
        float xv[12] = {a.x, a.y, a.z, a.w, b.x, b.y, b.z, b.w, c.x, c.y, c.z, c.w};

        unsigned long long xb[9];
#pragma unroll
        for (int m = 0; m < 9; ++m) xb[m] = pack2(xv[OFS + m]);

        // W pairs (j even, j odd) contiguous -> single 64-bit smem loads
        unsigned long long w0 = wp[0];
        unsigned long long w1 = wp[2048];   // k=1 plane: 128*16 ull
        unsigned long long w2 = wp[4096];   // k=2 plane

#pragma unroll
        for (int dw = 0; dw < 7; ++dw) {
            fma2(acc[dw], w0, xb[dw]);
            fma2(acc[dw], w1, xb[dw + 1]);
            fma2(acc[dw], w2, xb[dw + 2]);
        }

        xrow += XS_STRIDE;
        wp   += 16;     // 16 ull = 32 floats = one i row of W
    }
}

__global__ void __launch_bounds__(THREADS, 2)
conv3_kernel(const float* __restrict__ x, const float* __restrict__ W,
             float* __restrict__ out) {
    extern __shared__ float smem[];
    float* xs = smem;                 // [SLICES][NCH][16]
    float* ws = smem + XS_SIZE;       // [3][NCH][NJ]

    const int t = threadIdx.x;
    const int slice0 = blockIdx.x * SLICES;

    // ---- stage W into smem, layout ws[(k*128 + i)*32 + j] = W[j,k,i] ----
    // consecutive threads -> consecutive j: conflict-free STS; LDG strided but L1-cached.
    for (int idx = t; idx < WS_SIZE; idx += THREADS) {
        int j = idx & 31;
        int i = (idx >> 5) & 127;
        int k = idx >> 12;
        ws[idx] = W[j * 384 + k * 128 + i];
    }

    // ---- zero pad columns (positions 0 and 15) ----
    for (int idx = t; idx < SLICES * NCH; idx += THREADS) {
        xs[idx * XS_STRIDE + 0]  = 0.f;
        xs[idx * XS_STRIDE + 15] = 0.f;
    }

    // ---- stage x with width-roll(+1): position p=1..14 holds xr[w=p-1]=x[(p-2) mod 14] ----
    for (int idx = t; idx < SLICES * NCH * HW; idx += THREADS) {
        int w = idx % 14;
        int r = idx / 14;
        int i = r & 127;
        int s = r >> 7;
        int slice = slice0 + s;
        int n = slice / 14, h = slice % 14;
        float v = x[((n * NCH + i) * HW + h) * HW + w];
        int p = 1 + ((w + 1) % 14);
        xs[(s * NCH + i) * XS_STRIDE + p] = v;
    }
    __syncthreads();

    // ---- compute mapping: jg = j-pair, s = slice, wg warp-uniform (w-half) ----
    const int jg = t & 15;
    const int s  = (t >> 4) & 3;
    const int wg = t >> 6;            // warps 0,1 -> wg 0; warps 2,3 -> wg 1

    const float* xrow = xs + s * NCH * XS_STRIDE + wg * 4;  // window base 0 or 4
    const unsigned long long* wp = (const unsigned long long*)ws + jg;

    unsigned long long acc[7] = {0, 0, 0, 0, 0, 0, 0};
    if (wg == 0) run_i_loop<0>(xrow, wp, acc);
    else         run_i_loop<3>(xrow, wp, acc);

    // ---- write out with height-roll(+1) ----
    const int slice = slice0 + s;
    const int n = slice / 14, h = slice % 14;
    const int h2 = (h + 1 == 14) ? 0 : h + 1;
    const int w0 = wg * 7;
    float* op = out + ((n * NJ + 2 * jg) * HW + h2) * HW + w0;
#pragma unroll
    for (int dw = 0; dw < 7; ++dw) {
        unsigned long long v = acc[dw];
        op[dw]       = __uint_as_float((unsigned)(v & 0xffffffffu));  // j even
        op[dw + 196] = __uint_as_float((unsigned)(v >> 32));          // j odd (+14*14)
    }
}

extern "C" void kernel_launch(void* const* d_in, const int* in_sizes, int n_in,
                              void* d_out, int out_size) {
    const float* x = (const float*)d_in[0];   // (128,128,14,14) fp32
    const float* W = (const float*)d_in[1];   // (32,3,128) fp32
    float* out = (float*)d_out;               // (128,32,14,14) fp32

    cudaFuncSetAttribute(conv3_kernel,
                         cudaFuncAttributeMaxDynamicSharedMemorySize, SMEM_BYTES);
    // 1792 (n,h) slices / 4 per block = 448 blocks
    conv3_kernel<<<448, THREADS, SMEM_BYTES>>>(x, W, out);
}

// round 2
// speedup vs baseline: 1.5209x; 1.5209x over previous
#include <cuda_runtime.h>
#include <cstdint>

typedef unsigned long long ull;

#define NCH 128      // input channels i
#define HW  14       // spatial h, w
#define NJ  32       // output channels j
#define G   2        // (n,h) slices per block
#define THREADS 64

// W transposed to [k][i][j] so a (j even, j odd) pair is one 64-bit word.
__device__ float Wt[3 * NCH * NJ];   // 12288 floats = 48 KB, L1-resident

__global__ void wt_kernel(const float* __restrict__ W) {
    int idx = blockIdx.x * blockDim.x + threadIdx.x;
    if (idx < 3 * NCH * NJ) {
        int j = idx & 31;
        int i = (idx >> 5) & 127;
        int k = idx >> 12;
        Wt[idx] = W[j * 384 + k * 128 + i];   // W[j,k,i]
    }
}

__device__ __forceinline__ ull pack2(float v) {
    ull r;
    asm("mov.b64 %0, {%1, %1};" : "=l"(r) : "f"(v));
    return r;
}

__device__ __forceinline__ void fma2(ull& d, ull a, ull b) {
    asm("fma.rn.f32x2 %0, %1, %2, %0;" : "+l"(d) : "l"(a), "l"(b));
}

// One K-step: 21 packed FMAs on the current operands.
template <int OFS>
__device__ __forceinline__ void step(const float4& ca, const float4& cb, const float4& cc,
                                     ull w0, ull w1, ull w2, ull (&acc)[7]) {
    float xv[12] = {ca.x, ca.y, ca.z, ca.w, cb.x, cb.y, cb.z, cb.w,
                    cc.x, cc.y, cc.z, cc.w};
    ull xb[9];
#pragma unroll
    for (int m = 0; m < 9; ++m) xb[m] = pack2(xv[OFS + m]);
#pragma unroll
    for (int dw = 0; dw < 7; ++dw) {
        fma2(acc[dw], w0, xb[dw]);
        fma2(acc[dw], w1, xb[dw + 1]);
        fma2(acc[dw], w2, xb[dw + 2]);
    }
}

// Software-pipelined K loop: load i+1 (x from smem, W from L1) while computing i.
template <int OFS>
__device__ __forceinline__ void run_i_loop(const float* xrow, const ull* wp, ull (&acc)[7]) {
    float4 a = *(const float4*)(xrow);
    float4 b = *(const float4*)(xrow + 4);
    float4 c = *(const float4*)(xrow + 8);
    ull w0 = __ldg(wp), w1 = __ldg(wp + 2048), w2 = __ldg(wp + 4096);
#pragma unroll 2
    for (int i = 0; i < NCH - 1; ++i) {
        float4 ca = a, cb = b, cc = c;
        ull cw0 = w0, cw1 = w1, cw2 = w2;
        xrow += 16; wp += 16;
        a = *(const float4*)(xrow);
        b = *(const float4*)(xrow + 4);
        c = *(const float4*)(xrow + 8);
        w0 = __ldg(wp); w1 = __ldg(wp + 2048); w2 = __ldg(wp + 4096);
        step<OFS>(ca, cb, cc, cw0, cw1, cw2, acc);
    }
    step<OFS>(a, b, c, w0, w1, w2, acc);
}

__global__ void __launch_bounds__(THREADS)
conv3_kernel(const float* __restrict__ x, float* __restrict__ out) {
    __shared__ float xs[G * NCH * 16];   // 16 KB: [s][i][16] rows, pos 0/15 = zero pad

    const int t = threadIdx.x;
    const int slice0 = blockIdx.x * G;

    // zero pad columns
    for (int r = t; r < G * NCH; r += THREADS) {
        xs[r * 16 + 0]  = 0.f;
        xs[r * 16 + 15] = 0.f;
    }

    // stage x with width-roll(+1): position p = 1 + ((w+1) % 14) holds x[..., w].
    // Pairs (w, w+1), w even, map to contiguous p = (w+2, w+3), except (12,13) -> (14, 1).
    for (int idx = t; idx < G * NCH * 7; idx += THREADS) {
        int pi = idx % 7;            // pair index, w = 2*pi
        int r  = idx / 7;            // s*128 + i
        int s = r >> 7, i = r & 127;
        int slice = slice0 + s;
        int n = slice / 14, h = slice % 14;
        // row base element offset is even -> 8B aligned; streaming (read-once) load
        float2 v = __ldcs((const float2*)(x + ((n * NCH + i) * HW + h) * HW + 2 * pi));
        float* row = xs + r * 16;
        if (pi < 6) {
            *(float2*)(row + 2 * pi + 2) = v;
        } else {                     // w = 12, 13
            row[14] = v.x;
            row[1]  = v.y;
        }
    }
    __syncthreads();

    // thread roles: jg = j-pair (16), s = slice (2), wg = w-half (warp-uniform)
    const int jg = t & 15;
    const int s  = (t >> 4) & 1;
    const int wg = t >> 5;

    const float* xrow = xs + s * NCH * 16 + wg * 4;
    const ull* wp = (const ull*)Wt + jg;

    ull acc[7] = {0, 0, 0, 0, 0, 0, 0};
    if (wg == 0) run_i_loop<0>(xrow, wp, acc);
    else         run_i_loop<3>(xrow, wp, acc);

    // write out with height-roll(+1)
    const int slice = slice0 + s;
    const int n = slice / 14, h = slice % 14;
    const int h2 = (h + 1 == 14) ? 0 : h + 1;
    const int w0 = wg * 7;
    float* op = out + ((n * NJ + 2 * jg) * HW + h2) * HW + w0;
#pragma unroll
    for (int dw = 0; dw < 7; ++dw) {
        ull v = acc[dw];
        op[dw]       = __uint_as_float((unsigned)(v & 0xffffffffu));  // j even
        op[dw + 196] = __uint_as_float((unsigned)(v >> 32));          // j odd
    }
}

extern "C" void kernel_launch(void* const* d_in, const int* in_sizes, int n_in,
                              void* d_out, int out_size) {
    const float* x = (const float*)d_in[0];   // (128,128,14,14) fp32
    const float* W = (const float*)d_in[1];   // (32,3,128) fp32
    float* out = (float*)d_out;               // (128,32,14,14) fp32

    wt_kernel<<<12, 1024>>>(W);
    conv3_kernel<<<(128 * HW) / G, THREADS>>>(x, out);   // 896 blocks
}

// round 3
// speedup vs baseline: 1.8224x; 1.1982x over previous
#include <cuda_runtime.h>
#include <cstdint>

typedef unsigned long long ull;

#define NCH 128      // input channels i
#define HW  14       // spatial h, w
#define NJ  32       // output channels j
#define G   4        // (n,h) slices per block
#define THREADS 128

#define XS_SIZE  (G * NCH * 16)                   // 8192 floats = 32 KB
#define WS_SIZE  (3 * NCH * NJ)                   // 12288 floats = 48 KB, [k][i][j]
#define SMEM_BYTES ((XS_SIZE + WS_SIZE) * 4)      // 81920 B -> 2 CTAs/SM

// W transposed to [k][i][j] so a (j even, j odd) pair is one 64-bit word.
__device__ __align__(16) float Wt[WS_SIZE];

__global__ void wt_kernel(const float* __restrict__ W) {
    int idx = blockIdx.x * blockDim.x + threadIdx.x;
    if (idx < WS_SIZE) {
        int j = idx & 31;
        int i = (idx >> 5) & 127;
        int k = idx >> 12;
        Wt[idx] = W[j * 384 + k * 128 + i];   // W[j,k,i]
    }
}

__device__ __forceinline__ ull pack2(float v) {
    ull r;
    asm("mov.b64 %0, {%1, %1};" : "=l"(r) : "f"(v));
    return r;
}

__device__ __forceinline__ void fma2(ull& d, ull a, ull b) {
    asm("fma.rn.f32x2 %0, %1, %2, %0;" : "+l"(d) : "l"(a), "l"(b));
}

// One K-step: 21 packed FMAs.
template <int OFS>
__device__ __forceinline__ void step(const float4& ca, const float4& cb, const float4& cc,
                                     ull w0, ull w1, ull w2, ull (&acc)[7]) {
    float xv[12] = {ca.x, ca.y, ca.z, ca.w, cb.x, cb.y, cb.z, cb.w,
                    cc.x, cc.y, cc.z, cc.w};
    ull xb[9];
#pragma unroll
    for (int m = 0; m < 9; ++m) xb[m] = pack2(xv[OFS + m]);
#pragma unroll
    for (int dw = 0; dw < 7; ++dw) {
        fma2(acc[dw], w0, xb[dw]);
        fma2(acc[dw], w1, xb[dw + 1]);
        fma2(acc[dw], w2, xb[dw + 2]);
    }
}

// Manually 2x-unrolled, explicitly double-buffered pipeline.
// x from smem (broadcast LDS.128), W from smem (LDS.64, 29-cyc deterministic).
template <int OFS>
__device__ __forceinline__ void run_i_loop(const float* xrow, const ull* wp, ull (&acc)[7]) {
    float4 xa0, xb0, xc0, xa1, xb1, xc1;
    ull w00, w10, w20, w01, w11, w21;

    xa0 = *(const float4*)(xrow + 0);
    xb0 = *(const float4*)(xrow + 4);
    xc0 = *(const float4*)(xrow + 8);
    w00 = wp[0]; w10 = wp[2048]; w20 = wp[4096];

#pragma unroll 1
    for (int i = 0; i < 126; i += 2) {
        // prefetch i+1
        xa1 = *(const float4*)(xrow + 16);
        xb1 = *(const float4*)(xrow + 20);
        xc1 = *(const float4*)(xrow + 24);
        w01 = wp[16]; w11 = wp[2064]; w21 = wp[4112];
        step<OFS>(xa0, xb0, xc0, w00, w10, w20, acc);
        // prefetch i+2
        xa0 = *(const float4*)(xrow + 32);
        xb0 = *(const float4*)(xrow + 36);
        xc0 = *(const float4*)(xrow + 40);
        w00 = wp[32]; w10 = wp[2080]; w20 = wp[4128];
        step<OFS>(xa1, xb1, xc1, w01, w11, w21, acc);
        xrow += 32;
        wp   += 32;
    }
    // i = 126 in buf0, prefetch 127, drain
    xa1 = *(const float4*)(xrow + 16);
    xb1 = *(const float4*)(xrow + 20);
    xc1 = *(const float4*)(xrow + 24);
    w01 = wp[16]; w11 = wp[2064]; w21 = wp[4112];
    step<OFS>(xa0, xb0, xc0, w00, w10, w20, acc);
    step<OFS>(xa1, xb1, xc1, w01, w11, w21, acc);
}

__global__ void __launch_bounds__(THREADS, 2)
conv3_kernel(const float* __restrict__ x, float* __restrict__ out) {
    extern __shared__ float smem[];
    float* xs = smem;                 // [G][NCH][16], pos 0/15 zero pad
    float* ws = smem + XS_SIZE;       // [3][NCH][NJ]

    const int t = threadIdx.x;
    const int slice0 = blockIdx.x * G;

    // ---- stage W: coalesced float4 copy from pre-transposed Wt ----
    {
        const float4* src = (const float4*)Wt;
        float4* dst = (float4*)ws;
#pragma unroll
        for (int r = 0; r < WS_SIZE / 4 / THREADS; ++r)
            dst[r * THREADS + t] = src[r * THREADS + t];
    }

    // ---- zero pad columns ----
    for (int r = t; r < G * NCH; r += THREADS) {
        xs[r * 16 + 0]  = 0.f;
        xs[r * 16 + 15] = 0.f;
    }

    // ---- stage x with width-roll(+1): pos p = 1 + ((w+1) % 14) holds x[..., w] ----
    for (int idx = t; idx < G * NCH * 7; idx += THREADS) {
        int pi = idx % 7;            // pair index, w = 2*pi
        int r  = idx / 7;            // s*128 + i
        int s = r >> 7, i = r & 127;
        int slice = slice0 + s;
        int n = slice / 14, h = slice % 14;
        float2 v = __ldcs((const float2*)(x + ((n * NCH + i) * HW + h) * HW + 2 * pi));
        float* row = xs + r * 16;
        if (pi < 6) {
            *(float2*)(row + 2 * pi + 2) = v;
        } else {                     // w = 12, 13
            row[14] = v.x;
            row[1]  = v.y;
        }
    }
    __syncthreads();

    // ---- roles: jg = j-pair (16), s = slice (4), wg = w-half (warp-uniform: t>>6) ----
    const int jg = t & 15;
    const int s  = (t >> 4) & 3;
    const int wg = t >> 6;

    const float* xrow = xs + s * NCH * 16 + wg * 4;
    const ull* wp = (const ull*)ws + jg;

    ull acc[7] = {0, 0, 0, 0, 0, 0, 0};
    if (wg == 0) run_i_loop<0>(xrow, wp, acc);
    else         run_i_loop<3>(xrow, wp, acc);

    // ---- write out with height-roll(+1) ----
    const int slice = slice0 + s;
    const int n = slice / 14, h = slice % 14;
    const int h2 = (h + 1 == 14) ? 0 : h + 1;
    const int w0 = wg * 7;
    float* op = out + ((n * NJ + 2 * jg) * HW + h2) * HW + w0;
#pragma unroll
    for (int dw = 0; dw < 7; ++dw) {
        ull v = acc[dw];
        op[dw]       = __uint_as_float((unsigned)(v & 0xffffffffu));  // j even
        op[dw + 196] = __uint_as_float((unsigned)(v >> 32));          // j odd
    }
}

extern "C" void kernel_launch(void* const* d_in, const int* in_sizes, int n_in,
                              void* d_out, int out_size) {
    const float* x = (const float*)d_in[0];   // (128,128,14,14) fp32
    const float* W = (const float*)d_in[1];   // (32,3,128) fp32
    float* out = (float*)d_out;               // (128,32,14,14) fp32

    wt_kernel<<<12, 1024>>>(W);

    cudaFuncSetAttribute(conv3_kernel,
                         cudaFuncAttributeMaxDynamicSharedMemorySize, SMEM_BYTES);
    conv3_kernel<<<(128 * HW) / G, THREADS, SMEM_BYTES>>>(x, out);   // 448 blocks
}